// round 7
// baseline (speedup 1.0000x reference)
#include <cuda_runtime.h>

// JaggedConv2D: per-channel depthwise conv, ragged odd kernels 5..29 centered
// in 29x29 window, SAME padding. B=4, C=128, H=W=256, fp32.
//
// R7: packed fp32x2 FMA (fma.rn.f32x2) — 2 MACs per fma-pipe slot.
//   Output pairs (2p,2p+1) in 64-bit accumulators; even input pairs come free
//   from LDS.128 register quads, odd pairs built with MOV packs; weight splat
//   packed per tap on the ALU pipe. Conflict-free parity-pair lane mapping.

#define BB 4
#define CC 128
#define HH 256
#define WW 256
#define KMAXSZ 29

#define TW 64
#define TH 64
#define RX 8
#define RY 2
#define NTH 256

#define WT_OFF 848   // floats; 29*29=841 rounded up, 16B aligned

typedef unsigned long long ull;

__device__ __forceinline__ ull pk2(float a, float b) {
    ull r;
    asm("mov.b64 %0, {%1, %2};" : "=l"(r) : "f"(a), "f"(b));
    return r;
}

__device__ __forceinline__ ull fma2(ull a, ull b, ull c) {
    ull d;
    asm("fma.rn.f32x2 %0, %1, %2, %3;" : "=l"(d) : "l"(a), "l"(b), "l"(c));
    return d;
}

template<int K>
__device__ __forceinline__ void conv_body(const float* __restrict__ x,
                                          const float* __restrict__ kern,
                                          float* __restrict__ out,
                                          int ch, int b, float* smem)
{
    constexpr int HALO = K / 2;
    constexpr int IW   = TW + K - 1;
    constexpr int IH   = TH + K - 1;
    constexpr int NV   = (K + 10) / 4;              // float4 loads per vin row
    constexpr int PE   = 2 * NV;                    // even-aligned pairs
    constexpr int PO   = 2 * NV - 1;                // odd-aligned pairs
    constexpr int REACH = (TW - RX) + 4 * NV;
    constexpr int SW0 = (((IW > REACH) ? IW : REACH) + 3) & ~3;
    constexpr int SW  = ((SW0 >> 2) & 1) ? SW0 : SW0 + 4;  // force SW/4 odd
    constexpr int S    = (KMAXSZ - K) / 2;

    float* sWt = smem;
    float* sIn = smem + WT_OFF;

    const int tid = threadIdx.x;
    const int tileX0 = blockIdx.x * TW;
    const int tileY0 = blockIdx.y * TH;

    // ---- weights: ragged KxK window of the 29x29 kernel ----
    const float* kbase = kern + (size_t)ch * KMAXSZ * KMAXSZ;
    #pragma unroll 1
    for (int i = tid; i < K * K; i += NTH) {
        int ky = i / K, kx = i % K;
        sWt[i] = kbase[(S + ky) * KMAXSZ + (S + kx)];
    }

    // ---- input tile (+halo) into smem, zero-padded (incl. SW padding cols) ----
    const float* xbase = x + (size_t)(b * CC + ch) * HH * WW;
    const int inY0 = tileY0 - HALO;
    const int inX0 = tileX0 - HALO;
    #pragma unroll 1
    for (int idx = tid; idx < IH * SW; idx += NTH) {
        int r = idx / SW, c = idx - r * SW;
        int gy = inY0 + r, gx = inX0 + c;
        float v = 0.0f;
        if (c < IW && gy >= 0 && gy < HH && gx >= 0 && gx < WW)
            v = xbase[gy * WW + gx];
        sIn[idx] = v;
    }
    __syncthreads();

    // ---- conflict-free parity-pair lane mapping ----
    // tid: b0=parity, b1-b3=tx, b4-b7=row group (16 groups x 4 rows = 64 rows)
    const int parity = tid & 1;
    const int tx     = (tid >> 1) & 7;
    const int rg     = tid >> 4;
    const int c0 = tx * RX;                  // 32B aligned
    const int r0 = rg * 4 + parity;          // rows r0 + 2i, i=0..RY-1

    ull acc[RY][RX / 2];
    #pragma unroll
    for (int i = 0; i < RY; i++)
        #pragma unroll
        for (int p = 0; p < RX / 2; p++)
            acc[i][p] = 0ull;

    #pragma unroll 1
    for (int ky = 0; ky < K; ky++) {
        float wrow[K];
        #pragma unroll
        for (int kx = 0; kx < K; kx++)
            wrow[kx] = sWt[ky * K + kx];

        #pragma unroll
        for (int i = 0; i < RY; i++) {
            const float* rp = &sIn[(r0 + 2 * i + ky) * SW + c0];

            float vin[NV * 4];
            #pragma unroll
            for (int t = 0; t < NV; t++) {
                float4 q = *reinterpret_cast<const float4*>(rp + 4 * t);
                vin[4 * t + 0] = q.x; vin[4 * t + 1] = q.y;
                vin[4 * t + 2] = q.z; vin[4 * t + 3] = q.w;
            }

            // even pairs (free: register-quad aligned) and odd pairs (2 MOV)
            ull pe[PE], po[PO];
            #pragma unroll
            for (int e = 0; e < PE; e++)
                pe[e] = pk2(vin[2 * e], vin[2 * e + 1]);
            #pragma unroll
            for (int o = 0; o < PO; o++)
                po[o] = pk2(vin[2 * o + 1], vin[2 * o + 2]);

            #pragma unroll
            for (int kx = 0; kx < K; kx++) {
                ull w2 = pk2(wrow[kx], wrow[kx]);
                #pragma unroll
                for (int p = 0; p < RX / 2; p++) {
                    int off = kx + 2 * p;
                    ull v = (off & 1) ? po[off >> 1] : pe[off >> 1];
                    acc[i][p] = fma2(w2, v, acc[i][p]);
                }
            }
        }
    }

    // ---- store: 4 x 8B per row per thread ----
    float* obase = out + (size_t)(b * CC + ch) * HH * WW;
    #pragma unroll
    for (int i = 0; i < RY; i++) {
        ull* op = reinterpret_cast<ull*>(
            &obase[(size_t)(tileY0 + r0 + 2 * i) * WW + tileX0 + c0]);
        #pragma unroll
        for (int p = 0; p < RX / 2; p++)
            op[p] = acc[i][p];
    }
}

__global__ __launch_bounds__(NTH, 2)
void jagged_conv(const float* __restrict__ x,
                 const float* __restrict__ kern,
                 float* __restrict__ out)
{
    extern __shared__ float smem[];
    const int z  = blockIdx.z;
    const int ch = (CC - 1) - (z >> 2);   // descending K: big kernels first
    const int b  = z & 3;

    // k_i = floor(5 + 24*i/127), forced odd (matches np.linspace/astype)
    int k = 5 + (24 * ch) / 127;
    if ((k & 1) == 0) k -= 1;

    switch (k) {
        case  5: conv_body< 5>(x, kern, out, ch, b, smem); break;
        case  7: conv_body< 7>(x, kern, out, ch, b, smem); break;
        case  9: conv_body< 9>(x, kern, out, ch, b, smem); break;
        case 11: conv_body<11>(x, kern, out, ch, b, smem); break;
        case 13: conv_body<13>(x, kern, out, ch, b, smem); break;
        case 15: conv_body<15>(x, kern, out, ch, b, smem); break;
        case 17: conv_body<17>(x, kern, out, ch, b, smem); break;
        case 19: conv_body<19>(x, kern, out, ch, b, smem); break;
        case 21: conv_body<21>(x, kern, out, ch, b, smem); break;
        case 23: conv_body<23>(x, kern, out, ch, b, smem); break;
        case 25: conv_body<25>(x, kern, out, ch, b, smem); break;
        case 27: conv_body<27>(x, kern, out, ch, b, smem); break;
        case 29: conv_body<29>(x, kern, out, ch, b, smem); break;
        default: break;
    }
}

extern "C" void kernel_launch(void* const* d_in, const int* in_sizes, int n_in,
                              void* d_out, int out_size)
{
    (void)in_sizes; (void)n_in; (void)out_size;
    const float* x    = (const float*)d_in[0];
    const float* kern = (const float*)d_in[1];
    float* out        = (float*)d_out;

    // smem sized for K=29: WT_OFF + (TH+28) * SW(29)=92 floats
    const int smem_bytes = (WT_OFF + (TH + 28) * 92) * (int)sizeof(float);
    cudaFuncSetAttribute(jagged_conv,
                         cudaFuncAttributeMaxDynamicSharedMemorySize, smem_bytes);

    dim3 grid(WW / TW, HH / TH, BB * CC);
    dim3 block(NTH, 1, 1);
    jagged_conv<<<grid, block, smem_bytes>>>(x, kern, out);
}

// round 8
// speedup vs baseline: 1.4538x; 1.4538x over previous
#include <cuda_runtime.h>

// JaggedConv2D: per-channel depthwise conv, ragged odd kernels 5..29 centered
// in 29x29 window, SAME padding. B=4, C=128, H=W=256, fp32.
//
// R8 (base: R6 scalar, 501us): issue-efficiency fixes.
//  - fill loop batched x8 (MLP=8) instead of serialized LDG->STS
//  - weights repacked to stride-32 smem rows; kx chunked by 16 taps with
//    uniform LDS.128 weight loads -> live regs ~72, no 29-reg wrow hog
//  - conflict-free parity-pair LDS.128 mapping kept (SW/4 odd)

#define BB 4
#define CC 128
#define HH 256
#define WW 256
#define KMAXSZ 29

#define TW 64
#define TH 128
#define RX 8
#define RY 4
#define NTH 256

#define WSTRIDE 32
#define WT_OFF  (WSTRIDE * KMAXSZ)   // 928 floats = 3712B (128B aligned)

template<int K, int KXO, int SW>
__device__ __forceinline__ void do_chunk(const float* __restrict__ sWtRow,
                                         const float* __restrict__ sIn,
                                         int rowBase, int c0,
                                         float acc[RY][RX])
{
    constexpr int KW  = (K - KXO < 16) ? (K - KXO) : 16;   // taps this chunk
    constexpr int NW4 = (KW + 3) / 4;                      // weight float4s
    constexpr int NVC = (KW + RX - 1 + 3) / 4;             // vin float4s

    // weights: uniform address across warp -> broadcast
    float w[NW4 * 4];
    #pragma unroll
    for (int t = 0; t < NW4; t++) {
        float4 q = *reinterpret_cast<const float4*>(sWtRow + KXO + 4 * t);
        w[4*t+0] = q.x; w[4*t+1] = q.y; w[4*t+2] = q.z; w[4*t+3] = q.w;
    }

    #pragma unroll
    for (int i = 0; i < RY; i++) {
        const float* rp = &sIn[(rowBase + 2 * i) * SW + c0 + KXO];
        float vin[NVC * 4];
        #pragma unroll
        for (int t = 0; t < NVC; t++) {
            float4 q = *reinterpret_cast<const float4*>(rp + 4 * t);
            vin[4*t+0] = q.x; vin[4*t+1] = q.y;
            vin[4*t+2] = q.z; vin[4*t+3] = q.w;
        }
        #pragma unroll
        for (int kx = 0; kx < KW; kx++)
            #pragma unroll
            for (int j = 0; j < RX; j++)
                acc[i][j] = fmaf(w[kx], vin[kx + j], acc[i][j]);
    }
}

template<int K>
__device__ __forceinline__ void conv_body(const float* __restrict__ x,
                                          const float* __restrict__ kern,
                                          float* __restrict__ out,
                                          int ch, int b, float* smem)
{
    constexpr int HALO = K / 2;
    constexpr int IW   = TW + K - 1;
    constexpr int IH   = TH + K - 1;
    constexpr int NCH  = (K + 15) / 16;                 // kx chunks
    constexpr int KWL  = K - 16 * (NCH - 1);            // last chunk taps
    constexpr int REACH = (TW - RX) + 16 * (NCH - 1) + (((KWL + RX - 1 + 3) / 4) * 4);
    constexpr int SW0 = (((IW > REACH) ? IW : REACH) + 3) & ~3;
    constexpr int SW  = ((SW0 >> 2) & 1) ? SW0 : SW0 + 4;   // SW/4 odd
    constexpr int S   = (KMAXSZ - K) / 2;

    float* sWt = smem;            // [K][WSTRIDE]
    float* sIn = smem + WT_OFF;   // [IH][SW], base 128B aligned

    const int tid = threadIdx.x;
    const int tileX0 = blockIdx.x * TW;
    const int tileY0 = blockIdx.y * TH;

    // ---- weights: ragged KxK window -> stride-32 rows, zero padded ----
    const float* kbase = kern + (size_t)ch * KMAXSZ * KMAXSZ;
    #pragma unroll 1
    for (int i = tid; i < K * WSTRIDE; i += NTH) {
        int ky = i >> 5, kx = i & 31;
        float v = 0.0f;
        if (kx < K)
            v = kbase[(S + ky) * KMAXSZ + (S + kx)];
        sWt[i] = v;
    }

    // ---- input tile (+halo), zero padded; batched x8 for MLP ----
    const float* xbase = x + (size_t)(b * CC + ch) * HH * WW;
    const int inY0 = tileY0 - HALO;
    const int inX0 = tileX0 - HALO;
    constexpr int TOTAL = IH * SW;
    constexpr int UF = 8;
    #pragma unroll 1
    for (int base = tid; base < TOTAL; base += NTH * UF) {
        float v[UF];
        #pragma unroll
        for (int u = 0; u < UF; u++) {
            int idx = base + u * NTH;
            v[u] = 0.0f;
            if (idx < TOTAL) {
                int r = idx / SW, c = idx - r * SW;
                int gy = inY0 + r, gx = inX0 + c;
                if (c < IW && gy >= 0 && gy < HH && gx >= 0 && gx < WW)
                    v[u] = xbase[gy * WW + gx];
            }
        }
        #pragma unroll
        for (int u = 0; u < UF; u++) {
            int idx = base + u * NTH;
            if (idx < TOTAL)
                sIn[idx] = v[u];
        }
    }
    __syncthreads();

    // ---- conflict-free parity-pair lane mapping ----
    const int parity = tid & 1;
    const int tx     = (tid >> 1) & 7;
    const int rg     = tid >> 4;             // 16 groups x 8 rows
    const int c0 = tx * RX;                  // 32B aligned
    const int r0 = rg * 8 + parity;          // rows r0 + 2i, i=0..RY-1

    float acc[RY][RX];
    #pragma unroll
    for (int i = 0; i < RY; i++)
        #pragma unroll
        for (int j = 0; j < RX; j++)
            acc[i][j] = 0.0f;

    #pragma unroll 1
    for (int ky = 0; ky < K; ky++) {
        const float* sWtRow = &sWt[ky * WSTRIDE];
        const int rowBase = r0 + ky;
        do_chunk<K, 0, SW>(sWtRow, sIn, rowBase, c0, acc);
        if constexpr (K > 16)
            do_chunk<K, 16, SW>(sWtRow, sIn, rowBase, c0, acc);
    }

    // ---- store: two float4 per row per thread ----
    float* obase = out + (size_t)(b * CC + ch) * HH * WW;
    #pragma unroll
    for (int i = 0; i < RY; i++) {
        float* op = &obase[(size_t)(tileY0 + r0 + 2 * i) * WW + tileX0 + c0];
        float4 v0, v1;
        v0.x = acc[i][0]; v0.y = acc[i][1]; v0.z = acc[i][2]; v0.w = acc[i][3];
        v1.x = acc[i][4]; v1.y = acc[i][5]; v1.z = acc[i][6]; v1.w = acc[i][7];
        *reinterpret_cast<float4*>(op)     = v0;
        *reinterpret_cast<float4*>(op + 4) = v1;
    }
}

__global__ __launch_bounds__(NTH, 3)
void jagged_conv(const float* __restrict__ x,
                 const float* __restrict__ kern,
                 float* __restrict__ out)
{
    extern __shared__ float smem[];
    const int z  = blockIdx.z;
    const int ch = (CC - 1) - (z >> 2);   // descending K: big kernels first
    const int b  = z & 3;

    // k_i = floor(5 + 24*i/127), forced odd (matches np.linspace/astype)
    int k = 5 + (24 * ch) / 127;
    if ((k & 1) == 0) k -= 1;

    switch (k) {
        case  5: conv_body< 5>(x, kern, out, ch, b, smem); break;
        case  7: conv_body< 7>(x, kern, out, ch, b, smem); break;
        case  9: conv_body< 9>(x, kern, out, ch, b, smem); break;
        case 11: conv_body<11>(x, kern, out, ch, b, smem); break;
        case 13: conv_body<13>(x, kern, out, ch, b, smem); break;
        case 15: conv_body<15>(x, kern, out, ch, b, smem); break;
        case 17: conv_body<17>(x, kern, out, ch, b, smem); break;
        case 19: conv_body<19>(x, kern, out, ch, b, smem); break;
        case 21: conv_body<21>(x, kern, out, ch, b, smem); break;
        case 23: conv_body<23>(x, kern, out, ch, b, smem); break;
        case 25: conv_body<25>(x, kern, out, ch, b, smem); break;
        case 27: conv_body<27>(x, kern, out, ch, b, smem); break;
        case 29: conv_body<29>(x, kern, out, ch, b, smem); break;
        default: break;
    }
}

extern "C" void kernel_launch(void* const* d_in, const int* in_sizes, int n_in,
                              void* d_out, int out_size)
{
    (void)in_sizes; (void)n_in; (void)out_size;
    const float* x    = (const float*)d_in[0];
    const float* kern = (const float*)d_in[1];
    float* out        = (float*)d_out;

    // smem sized for K=29: WT_OFF + (TH+28) * SW(29)=92 floats
    const int smem_bytes = (WT_OFF + (TH + 28) * 92) * (int)sizeof(float);
    cudaFuncSetAttribute(jagged_conv,
                         cudaFuncAttributeMaxDynamicSharedMemorySize, smem_bytes);

    dim3 grid(WW / TW, HH / TH, BB * CC);
    dim3 block(NTH, 1, 1);
    jagged_conv<<<grid, block, smem_bytes>>>(x, kern, out);
}

// round 9
// speedup vs baseline: 1.4542x; 1.0003x over previous
#include <cuda_runtime.h>

// JaggedConv2D: per-channel depthwise conv, ragged odd kernels 5..29 centered
// in 29x29 window, SAME padding. B=4, C=128, H=W=256, fp32.
//
// R9 (base: R8, 408us): occupancy push.
//  - TH 128->64, RY 4->2 -> smem 61KB->37.6KB, regs ~60
//  - __launch_bounds__(256,4): 4 blocks/SM = 32 warps (was 24)
//  - keeps: x8-batched fill (MLP), stride-32 weight rows + 16-tap chunks,
//    conflict-free parity-pair LDS.128 mapping (SW/4 odd)

#define BB 4
#define CC 128
#define HH 256
#define WW 256
#define KMAXSZ 29

#define TW 64
#define TH 64
#define RX 8
#define RY 2
#define NTH 256

#define WSTRIDE 32
#define WT_OFF  (WSTRIDE * KMAXSZ)   // 928 floats (128B aligned)

template<int K, int KXO, int SW>
__device__ __forceinline__ void do_chunk(const float* __restrict__ sWtRow,
                                         const float* __restrict__ sIn,
                                         int rowBase, int c0,
                                         float acc[RY][RX])
{
    constexpr int KW  = (K - KXO < 16) ? (K - KXO) : 16;   // taps this chunk
    constexpr int NW4 = (KW + 3) / 4;                      // weight float4s
    constexpr int NVC = (KW + RX - 1 + 3) / 4;             // vin float4s

    // weights: uniform address across warp -> broadcast
    float w[NW4 * 4];
    #pragma unroll
    for (int t = 0; t < NW4; t++) {
        float4 q = *reinterpret_cast<const float4*>(sWtRow + KXO + 4 * t);
        w[4*t+0] = q.x; w[4*t+1] = q.y; w[4*t+2] = q.z; w[4*t+3] = q.w;
    }

    #pragma unroll
    for (int i = 0; i < RY; i++) {
        const float* rp = &sIn[(rowBase + 2 * i) * SW + c0 + KXO];
        float vin[NVC * 4];
        #pragma unroll
        for (int t = 0; t < NVC; t++) {
            float4 q = *reinterpret_cast<const float4*>(rp + 4 * t);
            vin[4*t+0] = q.x; vin[4*t+1] = q.y;
            vin[4*t+2] = q.z; vin[4*t+3] = q.w;
        }
        #pragma unroll
        for (int kx = 0; kx < KW; kx++)
            #pragma unroll
            for (int j = 0; j < RX; j++)
                acc[i][j] = fmaf(w[kx], vin[kx + j], acc[i][j]);
    }
}

template<int K>
__device__ __forceinline__ void conv_body(const float* __restrict__ x,
                                          const float* __restrict__ kern,
                                          float* __restrict__ out,
                                          int ch, int b, float* smem)
{
    constexpr int HALO = K / 2;
    constexpr int IW   = TW + K - 1;
    constexpr int IH   = TH + K - 1;
    constexpr int NCH  = (K + 15) / 16;                 // kx chunks
    constexpr int KWL  = K - 16 * (NCH - 1);            // last chunk taps
    constexpr int REACH = (TW - RX) + 16 * (NCH - 1) + (((KWL + RX - 1 + 3) / 4) * 4);
    constexpr int SW0 = (((IW > REACH) ? IW : REACH) + 3) & ~3;
    constexpr int SW  = ((SW0 >> 2) & 1) ? SW0 : SW0 + 4;   // SW/4 odd
    constexpr int S   = (KMAXSZ - K) / 2;

    float* sWt = smem;            // [K][WSTRIDE]
    float* sIn = smem + WT_OFF;   // [IH][SW], base 128B aligned

    const int tid = threadIdx.x;
    const int tileX0 = blockIdx.x * TW;
    const int tileY0 = blockIdx.y * TH;

    // ---- weights: ragged KxK window -> stride-32 rows, zero padded ----
    const float* kbase = kern + (size_t)ch * KMAXSZ * KMAXSZ;
    #pragma unroll 1
    for (int i = tid; i < K * WSTRIDE; i += NTH) {
        int ky = i >> 5, kx = i & 31;
        float v = 0.0f;
        if (kx < K)
            v = kbase[(S + ky) * KMAXSZ + (S + kx)];
        sWt[i] = v;
    }

    // ---- input tile (+halo), zero padded; batched x8 for MLP ----
    const float* xbase = x + (size_t)(b * CC + ch) * HH * WW;
    const int inY0 = tileY0 - HALO;
    const int inX0 = tileX0 - HALO;
    constexpr int TOTAL = IH * SW;
    constexpr int UF = 8;
    #pragma unroll 1
    for (int base = tid; base < TOTAL; base += NTH * UF) {
        float v[UF];
        #pragma unroll
        for (int u = 0; u < UF; u++) {
            int idx = base + u * NTH;
            v[u] = 0.0f;
            if (idx < TOTAL) {
                int r = idx / SW, c = idx - r * SW;
                int gy = inY0 + r, gx = inX0 + c;
                if (c < IW && gy >= 0 && gy < HH && gx >= 0 && gx < WW)
                    v[u] = xbase[gy * WW + gx];
            }
        }
        #pragma unroll
        for (int u = 0; u < UF; u++) {
            int idx = base + u * NTH;
            if (idx < TOTAL)
                sIn[idx] = v[u];
        }
    }
    __syncthreads();

    // ---- conflict-free parity-pair lane mapping ----
    // tid: b0=parity, b1-b3=tx, b4-b7=row group (16 groups x 4 rows = 64)
    const int parity = tid & 1;
    const int tx     = (tid >> 1) & 7;
    const int rg     = tid >> 4;
    const int c0 = tx * RX;                  // 32B aligned
    const int r0 = rg * 4 + parity;          // rows r0 + 2i, i=0..RY-1

    float acc[RY][RX];
    #pragma unroll
    for (int i = 0; i < RY; i++)
        #pragma unroll
        for (int j = 0; j < RX; j++)
            acc[i][j] = 0.0f;

    #pragma unroll 1
    for (int ky = 0; ky < K; ky++) {
        const float* sWtRow = &sWt[ky * WSTRIDE];
        const int rowBase = r0 + ky;
        do_chunk<K, 0, SW>(sWtRow, sIn, rowBase, c0, acc);
        if constexpr (K > 16)
            do_chunk<K, 16, SW>(sWtRow, sIn, rowBase, c0, acc);
    }

    // ---- store: two float4 per row per thread ----
    float* obase = out + (size_t)(b * CC + ch) * HH * WW;
    #pragma unroll
    for (int i = 0; i < RY; i++) {
        float* op = &obase[(size_t)(tileY0 + r0 + 2 * i) * WW + tileX0 + c0];
        float4 v0, v1;
        v0.x = acc[i][0]; v0.y = acc[i][1]; v0.z = acc[i][2]; v0.w = acc[i][3];
        v1.x = acc[i][4]; v1.y = acc[i][5]; v1.z = acc[i][6]; v1.w = acc[i][7];
        *reinterpret_cast<float4*>(op)     = v0;
        *reinterpret_cast<float4*>(op + 4) = v1;
    }
}

__global__ __launch_bounds__(NTH, 4)
void jagged_conv(const float* __restrict__ x,
                 const float* __restrict__ kern,
                 float* __restrict__ out)
{
    extern __shared__ float smem[];
    const int z  = blockIdx.z;
    const int ch = (CC - 1) - (z >> 2);   // descending K: big kernels first
    const int b  = z & 3;

    // k_i = floor(5 + 24*i/127), forced odd (matches np.linspace/astype)
    int k = 5 + (24 * ch) / 127;
    if ((k & 1) == 0) k -= 1;

    switch (k) {
        case  5: conv_body< 5>(x, kern, out, ch, b, smem); break;
        case  7: conv_body< 7>(x, kern, out, ch, b, smem); break;
        case  9: conv_body< 9>(x, kern, out, ch, b, smem); break;
        case 11: conv_body<11>(x, kern, out, ch, b, smem); break;
        case 13: conv_body<13>(x, kern, out, ch, b, smem); break;
        case 15: conv_body<15>(x, kern, out, ch, b, smem); break;
        case 17: conv_body<17>(x, kern, out, ch, b, smem); break;
        case 19: conv_body<19>(x, kern, out, ch, b, smem); break;
        case 21: conv_body<21>(x, kern, out, ch, b, smem); break;
        case 23: conv_body<23>(x, kern, out, ch, b, smem); break;
        case 25: conv_body<25>(x, kern, out, ch, b, smem); break;
        case 27: conv_body<27>(x, kern, out, ch, b, smem); break;
        case 29: conv_body<29>(x, kern, out, ch, b, smem); break;
        default: break;
    }
}

extern "C" void kernel_launch(void* const* d_in, const int* in_sizes, int n_in,
                              void* d_out, int out_size)
{
    (void)in_sizes; (void)n_in; (void)out_size;
    const float* x    = (const float*)d_in[0];
    const float* kern = (const float*)d_in[1];
    float* out        = (float*)d_out;

    // smem sized for K=29: WT_OFF + IH(92) * SW(92) floats = 37568 B
    const int smem_bytes = (WT_OFF + (TH + 28) * 92) * (int)sizeof(float);
    cudaFuncSetAttribute(jagged_conv,
                         cudaFuncAttributeMaxDynamicSharedMemorySize, smem_bytes);

    dim3 grid(WW / TW, HH / TH, BB * CC);
    dim3 block(NTH, 1, 1);
    jagged_conv<<<grid, block, smem_bytes>>>(x, kern, out);
}

// round 11
// speedup vs baseline: 1.6517x; 1.1358x over previous
#include <cuda_runtime.h>

// JaggedConv2D: per-channel depthwise conv, ragged odd kernels 5..29 centered
// in 29x29 window, SAME padding. B=4, C=128, H=W=256, fp32.
//
// R11 (fix of R10 misalignment; base R9 = 408us):
//  - vectorized divide-free row fill (LDG.128/STS.128, MLP=4), 4-aligned
//    tile origin (HALO4)
//  - compute loads vin from ALIGNED floor of shifted base:
//    AOFF=(D+KXO)&~3 (16B-aligned), register shift OFF=(D+KXO)&3
//  - 16-tap weight chunks, parity-pair conflict-free LDS.128 (SW/4 odd)
//  - bit-identical accumulation order to R9

#define BB 4
#define CC 128
#define HH 256
#define WW 256
#define KMAXSZ 29

#define TW 64
#define TH 64
#define RX 8
#define RY 2
#define NTH 256

#define WSTRIDE 32
#define WT_OFF  (WSTRIDE * KMAXSZ)   // 928 floats (128B aligned)

template<int K, int KXO, int SW, int D>
__device__ __forceinline__ void do_chunk(const float* __restrict__ sWtRow,
                                         const float* __restrict__ sIn,
                                         int rowBase, int c0,
                                         float acc[RY][RX])
{
    constexpr int KW   = (K - KXO < 16) ? (K - KXO) : 16;   // taps this chunk
    constexpr int NW4  = (KW + 3) / 4;                      // weight float4s
    constexpr int AOFF = (D + KXO) & ~3;                    // aligned smem offset
    constexpr int OFF  = (D + KXO) & 3;                     // register shift
    constexpr int NVC  = (OFF + KW + RX - 1 + 3) / 4;       // vin float4s

    // weights: uniform address across warp -> broadcast
    float w[NW4 * 4];
    #pragma unroll
    for (int t = 0; t < NW4; t++) {
        float4 q = *reinterpret_cast<const float4*>(sWtRow + KXO + 4 * t);
        w[4*t+0] = q.x; w[4*t+1] = q.y; w[4*t+2] = q.z; w[4*t+3] = q.w;
    }

    #pragma unroll
    for (int i = 0; i < RY; i++) {
        const float* rp = &sIn[(rowBase + 2 * i) * SW + c0 + AOFF];  // 16B aligned
        float vin[NVC * 4];
        #pragma unroll
        for (int t = 0; t < NVC; t++) {
            float4 q = *reinterpret_cast<const float4*>(rp + 4 * t);
            vin[4*t+0] = q.x; vin[4*t+1] = q.y;
            vin[4*t+2] = q.z; vin[4*t+3] = q.w;
        }
        #pragma unroll
        for (int kx = 0; kx < KW; kx++)
            #pragma unroll
            for (int j = 0; j < RX; j++)
                acc[i][j] = fmaf(w[kx], vin[OFF + kx + j], acc[i][j]);
    }
}

template<int K>
__device__ __forceinline__ void conv_body(const float* __restrict__ x,
                                          const float* __restrict__ kern,
                                          float* __restrict__ out,
                                          int ch, int b, float* smem)
{
    constexpr int HALO  = K / 2;
    constexpr int HALO4 = (HALO + 3) & ~3;   // 4-aligned left halo
    constexpr int D     = HALO4 - HALO;      // logical column shift (0..3)
    constexpr int IH    = TH + K - 1;
    constexpr int IW    = TW + K - 1 + D;
    // reach per chunk: AOFF + 4*NVC
    constexpr int KW0   = (K < 16) ? K : 16;
    constexpr int R0    = ((D & ~3) /*=0*/) + 4 * (((D & 3) + KW0 + RX - 1 + 3) / 4);
    constexpr int KW1   = (K > 16) ? (K - 16) : 0;
    constexpr int R1    = (K > 16)
        ? (((D + 16) & ~3) + 4 * ((((D + 16) & 3) + KW1 + RX - 1 + 3) / 4))
        : 0;
    constexpr int RMAX  = (R0 > R1) ? R0 : R1;
    constexpr int REACH = (TW - RX) + RMAX;
    constexpr int SW0   = (((IW > REACH) ? IW : REACH) + 3) & ~3;
    constexpr int SW    = ((SW0 >> 2) & 1) ? SW0 : SW0 + 4;  // SW/4 odd
    constexpr int SW4   = SW / 4;
    constexpr int S     = (KMAXSZ - K) / 2;

    float* sWt = smem;            // [K][WSTRIDE]
    float* sIn = smem + WT_OFF;   // [IH][SW], base 128B aligned

    const int tid = threadIdx.x;
    const int tileX0 = blockIdx.x * TW;
    const int tileY0 = blockIdx.y * TH;

    // ---- weights: ragged KxK window -> stride-32 rows, zero padded ----
    const float* kbase = kern + (size_t)ch * KMAXSZ * KMAXSZ;
    #pragma unroll 1
    for (int i = tid; i < K * WSTRIDE; i += NTH) {
        int ky = i >> 5, kx = i & 31;
        float v = 0.0f;
        if (kx < K)
            v = kbase[(S + ky) * KMAXSZ + (S + kx)];
        sWt[i] = v;
    }

    // ---- input tile (+halo), vectorized row fill, zero padded ----
    // smem col c holds global x = tileX0 - HALO4 + c (4-aligned origin)
    {
        const float* xbase = x + (size_t)(b * CC + ch) * HH * WW;
        const int inY0 = tileY0 - HALO;
        const int inX0 = tileX0 - HALO4;
        const int lane = tid & 31;
        const int warp = tid >> 5;

        if (lane < SW4) {
            const int gx0 = inX0 + lane * 4;                 // 4-aligned
            const bool xfast = (gx0 >= 0) && (gx0 + 4 <= WW);
            #pragma unroll 1
            for (int rb = warp; rb < IH; rb += 32) {
                float4 v[4];
                #pragma unroll
                for (int u = 0; u < 4; u++) {
                    int r = rb + 8 * u;
                    v[u].x = 0.f; v[u].y = 0.f; v[u].z = 0.f; v[u].w = 0.f;
                    int gy = inY0 + r;
                    if (r < IH && (unsigned)gy < (unsigned)HH) {
                        const float* gp = xbase + (size_t)gy * WW + gx0;
                        if (xfast) {
                            v[u] = *reinterpret_cast<const float4*>(gp);
                        } else {
                            if ((unsigned)(gx0 + 0) < (unsigned)WW) v[u].x = gp[0];
                            if ((unsigned)(gx0 + 1) < (unsigned)WW) v[u].y = gp[1];
                            if ((unsigned)(gx0 + 2) < (unsigned)WW) v[u].z = gp[2];
                            if ((unsigned)(gx0 + 3) < (unsigned)WW) v[u].w = gp[3];
                        }
                    }
                }
                #pragma unroll
                for (int u = 0; u < 4; u++) {
                    int r = rb + 8 * u;
                    if (r < IH)
                        *reinterpret_cast<float4*>(&sIn[r * SW + lane * 4]) = v[u];
                }
            }
        }
    }
    __syncthreads();

    // ---- conflict-free parity-pair lane mapping ----
    const int parity = tid & 1;
    const int tx     = (tid >> 1) & 7;
    const int rg     = tid >> 4;
    const int c0 = tx * RX;                  // output col, 32B aligned
    const int r0 = rg * 4 + parity;          // rows r0 + 2i, i=0..RY-1

    float acc[RY][RX];
    #pragma unroll
    for (int i = 0; i < RY; i++)
        #pragma unroll
        for (int j = 0; j < RX; j++)
            acc[i][j] = 0.0f;

    #pragma unroll 1
    for (int ky = 0; ky < K; ky++) {
        const float* sWtRow = &sWt[ky * WSTRIDE];
        const int rowBase = r0 + ky;
        do_chunk<K, 0, SW, D>(sWtRow, sIn, rowBase, c0, acc);
        if constexpr (K > 16)
            do_chunk<K, 16, SW, D>(sWtRow, sIn, rowBase, c0, acc);
    }

    // ---- store: two float4 per row per thread ----
    float* obase = out + (size_t)(b * CC + ch) * HH * WW;
    #pragma unroll
    for (int i = 0; i < RY; i++) {
        float* op = &obase[(size_t)(tileY0 + r0 + 2 * i) * WW + tileX0 + c0];
        float4 v0, v1;
        v0.x = acc[i][0]; v0.y = acc[i][1]; v0.z = acc[i][2]; v0.w = acc[i][3];
        v1.x = acc[i][4]; v1.y = acc[i][5]; v1.z = acc[i][6]; v1.w = acc[i][7];
        *reinterpret_cast<float4*>(op)     = v0;
        *reinterpret_cast<float4*>(op + 4) = v1;
    }
}

__global__ __launch_bounds__(NTH, 4)
void jagged_conv(const float* __restrict__ x,
                 const float* __restrict__ kern,
                 float* __restrict__ out)
{
    extern __shared__ float smem[];
    const int z  = blockIdx.z;
    const int ch = (CC - 1) - (z >> 2);   // descending K: big kernels first
    const int b  = z & 3;

    // k_i = floor(5 + 24*i/127), forced odd (matches np.linspace/astype)
    int k = 5 + (24 * ch) / 127;
    if ((k & 1) == 0) k -= 1;

    switch (k) {
        case  5: conv_body< 5>(x, kern, out, ch, b, smem); break;
        case  7: conv_body< 7>(x, kern, out, ch, b, smem); break;
        case  9: conv_body< 9>(x, kern, out, ch, b, smem); break;
        case 11: conv_body<11>(x, kern, out, ch, b, smem); break;
        case 13: conv_body<13>(x, kern, out, ch, b, smem); break;
        case 15: conv_body<15>(x, kern, out, ch, b, smem); break;
        case 17: conv_body<17>(x, kern, out, ch, b, smem); break;
        case 19: conv_body<19>(x, kern, out, ch, b, smem); break;
        case 21: conv_body<21>(x, kern, out, ch, b, smem); break;
        case 23: conv_body<23>(x, kern, out, ch, b, smem); break;
        case 25: conv_body<25>(x, kern, out, ch, b, smem); break;
        case 27: conv_body<27>(x, kern, out, ch, b, smem); break;
        case 29: conv_body<29>(x, kern, out, ch, b, smem); break;
        default: break;
    }
}

extern "C" void kernel_launch(void* const* d_in, const int* in_sizes, int n_in,
                              void* d_out, int out_size)
{
    (void)in_sizes; (void)n_in; (void)out_size;
    const float* x    = (const float*)d_in[0];
    const float* kern = (const float*)d_in[1];
    float* out        = (float*)d_out;

    // max smem across K: K=29 -> WT_OFF(928) + IH(92)*SW(100) = 10128 floats
    const int smem_bytes = (WT_OFF + 92 * 100) * (int)sizeof(float);
    cudaFuncSetAttribute(jagged_conv,
                         cudaFuncAttributeMaxDynamicSharedMemorySize, smem_bytes);

    dim3 grid(WW / TW, HH / TH, BB * CC);
    dim3 block(NTH, 1, 1);
    jagged_conv<<<grid, block, smem_bytes>>>(x, kern, out);
}